// round 17
// baseline (speedup 1.0000x reference)
#include <cuda_runtime.h>
#include <cuda_fp16.h>
#include <math.h>

#define NROWS 4096
#define NW 128          // adjacency bitmask words per row
#define HID 64
#define ALPHA 0.2f
#define BRR 64          // attention rows per block
#define BM 64           // attention m-chunk
#define HBP 72          // attn h tile pitch in halves (144 B)
#define BUFBYTES (BM * HBP * 2)
#define XSP 40          // gemm A tile pitch in halves (80 B)
#define WSP 72          // gemm B tile pitch in halves (144 B)
#define XSB (64 * XSP)  // halves per A stage
#define WSB (32 * WSP)  // halves per B stage

// ---------------- device scratch ----------------
__device__ unsigned int g_adjbits[NROWS * NW];       // 2 MB packed adjacency
__device__ __half g_h16[4 * NROWS * HID];            // fp16 head features (mma B)
__device__ float g_el[4 * NROWS];
__device__ float g_er[4 * NROWS];
__device__ unsigned int g_emax_u[12];                // per (layer, head) max(e_r)
__device__ __half g_buf16[NROWS * 256];              // fp16 inter-layer activations
__device__ __half g_x16[NROWS * 128];                // fp16 copy of input x
__device__ __half g_W16[4 * 256 * 64 + 4 * 128 * 64 + 256 * 64];  // fp16 W0|W1|W2
__device__ float g_pnum[512 * BRR * HID];            // split-m partial numerators (8 MB)
__device__ float g_pden[512 * BRR];                  // split-m partial denominators
__device__ unsigned int g_fixcnt[768];               // fixup counters per (layer, rb, head)

#define W0OFF 0
#define W1OFF (4 * 128 * 64)
#define W2OFF (W1OFF + 4 * 256 * 64)

// ---------------- helpers ----------------
__device__ __forceinline__ unsigned f2ord(float f) {
    unsigned u = __float_as_uint(f);
    return (u & 0x80000000u) ? ~u : (u | 0x80000000u);
}
__device__ __forceinline__ float ord2f(unsigned u) {
    return (u & 0x80000000u) ? __uint_as_float(u ^ 0x80000000u) : __uint_as_float(~u);
}
__device__ __forceinline__ unsigned long long packAC(float a, float c) {
    unsigned long long r;
    asm("mov.b64 %0, {%1, %2};" : "=l"(r) : "f"(a), "f"(c));
    return r;
}
__device__ __forceinline__ float2 mul2(unsigned long long a, unsigned long long b) {
    unsigned long long r;
    asm("mul.rn.f32x2 %0, %1, %2;" : "=l"(r) : "l"(a), "l"(b));
    float2 f;
    asm("mov.b64 {%0, %1}, %2;" : "=f"(f.x), "=f"(f.y) : "l"(r));
    return f;
}
__device__ __forceinline__ void mma16816(float* c, unsigned a0, unsigned a1,
                                         unsigned a2, unsigned a3,
                                         unsigned b0, unsigned b1) {
    asm volatile(
        "mma.sync.aligned.m16n8k16.row.col.f32.f16.f16.f32 "
        "{%0,%1,%2,%3}, {%4,%5,%6,%7}, {%8,%9}, {%0,%1,%2,%3};"
        : "+f"(c[0]), "+f"(c[1]), "+f"(c[2]), "+f"(c[3])
        : "r"(a0), "r"(a1), "r"(a2), "r"(a3), "r"(b0), "r"(b1));
}
__device__ __forceinline__ void cpasync16(unsigned dst, const void* src) {
    asm volatile("cp.async.cg.shared.global [%0], [%1], 16;" :: "r"(dst), "l"(src));
}

// ---------------- 1. pack adjacency (+ reset emax and fixup counters) ----------------
__global__ void pack_adj_kernel(const int* __restrict__ adj) {
    if (blockIdx.x == 0) {
        for (int i = threadIdx.x; i < 768; i += 128) g_fixcnt[i] = 0u;
        if (threadIdx.x < 12) g_emax_u[threadIdx.x] = 0u;
    }
    int n = blockIdx.x;
    int warp = threadIdx.x >> 5, lane = threadIdx.x & 31;
    const int* row = adj + (size_t)n * NROWS;
    #pragma unroll 4
    for (int w = warp * 32; w < warp * 32 + 32; w++) {
        int v = row[w * 32 + lane];
        unsigned int bits = __ballot_sync(0xffffffffu, v > 0);
        if (lane == 0) g_adjbits[n * NW + w] = bits;
    }
}

// ---------------- 2. fp16 conversions of x and weights ----------------
__global__ void convert_kernel(const float* __restrict__ x,
                               const float* __restrict__ W0,
                               const float* __restrict__ W1,
                               const float* __restrict__ W2) {
    int t = blockIdx.x * blockDim.x + threadIdx.x;
    int stride = gridDim.x * blockDim.x;
    for (int i = t; i < NROWS * 128; i += stride) g_x16[i] = __float2half_rn(x[i]);
    for (int i = t; i < 4 * 128 * 64; i += stride) g_W16[W0OFF + i] = __float2half_rn(W0[i]);
    for (int i = t; i < 4 * 256 * 64; i += stride) g_W16[W1OFF + i] = __float2half_rn(W1[i]);
    for (int i = t; i < 256 * 64; i += stride) g_W16[W2OFF + i] = __float2half_rn(W2[i]);
}

// ---------------- 3. fp16 tensor-core feature GEMM + fused e epilogue ----------------
__global__ __launch_bounds__(128, 3) void gemm16_kernel(const __half* __restrict__ X16,
                                                        const __half* __restrict__ W16,
                                                        const float* __restrict__ a,
                                                        int D, int layer) {
    const int head = blockIdx.y;
    const int r0 = blockIdx.x * 64;
    const int tid = threadIdx.x;
    const int lane = tid & 31, w = tid >> 5;

    __shared__ __align__(16) __half Xs[3][XSB];
    __shared__ __align__(16) __half Ws[3][WSB];
    __shared__ float erow[64];

    float acc[8][4];
    #pragma unroll
    for (int nt = 0; nt < 8; nt++)
        #pragma unroll
        for (int c = 0; c < 4; c++) acc[nt][c] = 0.f;

    const int grp = lane >> 3, li = lane & 7;
    const int arow = w * 16 + li + (grp & 1) * 8;
    const unsigned aS = (unsigned)__cvta_generic_to_shared(
        &Xs[0][arow * XSP + (grp >> 1) * 8]);
    const unsigned bS = (unsigned)__cvta_generic_to_shared(
        &Ws[0][((grp & 1) * 8 + li) * WSP + (grp >> 1) * 8]);

    int axr[2], axc[2], bkr[2], bkc[2];
    unsigned adst[2], bdst[2];
    const unsigned XsS = (unsigned)__cvta_generic_to_shared(&Xs[0][0]);
    const unsigned WsS = (unsigned)__cvta_generic_to_shared(&Ws[0][0]);
    #pragma unroll
    for (int i = 0; i < 2; i++) {
        int idx = tid + i * 128;
        axr[i] = idx >> 2; axc[i] = (idx & 3) * 8;
        adst[i] = XsS + (unsigned)((axr[i] * XSP + axc[i]) * 2);
        bkr[i] = idx >> 3; bkc[i] = (idx & 7) * 8;
        bdst[i] = WsS + (unsigned)((bkr[i] * WSP + bkc[i]) * 2);
    }
    const __half* Wh = W16 + (size_t)head * D * HID;
    const int NCH = D / 32;

    #pragma unroll
    for (int i = 0; i < 2; i++) {
        cpasync16(adst[i], &X16[(size_t)(r0 + axr[i]) * D + axc[i]]);
        cpasync16(bdst[i], &Wh[(size_t)bkr[i] * HID + bkc[i]]);
    }
    asm volatile("cp.async.commit_group;" ::: "memory");

    int cur = 0;
    for (int ci = 0; ci < NCH; ci++) {
        const int k0 = ci * 32;
        const int nxt = (cur == 2) ? 0 : cur + 1;
        if (ci + 1 < NCH) {
            #pragma unroll
            for (int i = 0; i < 2; i++) {
                cpasync16(adst[i] + (unsigned)(nxt * XSB * 2),
                          &X16[(size_t)(r0 + axr[i]) * D + k0 + 32 + axc[i]]);
                cpasync16(bdst[i] + (unsigned)(nxt * WSB * 2),
                          &Wh[(size_t)(k0 + 32 + bkr[i]) * HID + bkc[i]]);
            }
        }
        asm volatile("cp.async.commit_group;" ::: "memory");
        asm volatile("cp.async.wait_group 1;" ::: "memory");
        __syncthreads();

        const unsigned aC = aS + (unsigned)(cur * XSB * 2);
        const unsigned bC = bS + (unsigned)(cur * WSB * 2);
        #pragma unroll
        for (int ks = 0; ks < 2; ks++) {
            unsigned a0, a1, a2, a3;
            asm volatile("ldmatrix.sync.aligned.m8n8.x4.shared.b16 {%0,%1,%2,%3}, [%4];"
                         : "=r"(a0), "=r"(a1), "=r"(a2), "=r"(a3)
                         : "r"(aC + ks * 32));
            #pragma unroll
            for (int np = 0; np < 4; np++) {
                unsigned b0, b1, b2, b3;
                asm volatile("ldmatrix.sync.aligned.m8n8.x4.trans.shared.b16 {%0,%1,%2,%3}, [%4];"
                             : "=r"(b0), "=r"(b1), "=r"(b2), "=r"(b3)
                             : "r"(bC + ks * (16 * WSP * 2) + np * 32));
                mma16816(acc[np * 2],     a0, a1, a2, a3, b0, b1);
                mma16816(acc[np * 2 + 1], a0, a1, a2, a3, b2, b3);
            }
        }
        __syncthreads();
        cur = nxt;
    }

    const int crow = w * 16 + (lane >> 2);
    const int ccol = (lane & 3) * 2;
    __half2* hp16 = (__half2*)(g_h16 + ((size_t)head * NROWS + r0) * HID);
    const float* ah = a + head * 2 * HID;
    float pl0 = 0.f, pr0 = 0.f, pl1 = 0.f, pr1 = 0.f;
    #pragma unroll
    for (int nt = 0; nt < 8; nt++) {
        int c = nt * 8 + ccol;
        hp16[(crow * HID + c) >> 1]       = __floats2half2_rn(acc[nt][0], acc[nt][1]);
        hp16[((crow + 8) * HID + c) >> 1] = __floats2half2_rn(acc[nt][2], acc[nt][3]);
        float al0 = ah[c], al1 = ah[c + 1];
        float ar0 = ah[HID + c], ar1 = ah[HID + c + 1];
        pl0 += acc[nt][0] * al0 + acc[nt][1] * al1;
        pr0 += acc[nt][0] * ar0 + acc[nt][1] * ar1;
        pl1 += acc[nt][2] * al0 + acc[nt][3] * al1;
        pr1 += acc[nt][2] * ar0 + acc[nt][3] * ar1;
    }
    #pragma unroll
    for (int off = 1; off <= 2; off <<= 1) {
        pl0 += __shfl_xor_sync(0xffffffffu, pl0, off);
        pr0 += __shfl_xor_sync(0xffffffffu, pr0, off);
        pl1 += __shfl_xor_sync(0xffffffffu, pl1, off);
        pr1 += __shfl_xor_sync(0xffffffffu, pr1, off);
    }
    if ((lane & 3) == 0) {
        g_el[head * NROWS + r0 + crow] = pl0;
        g_er[head * NROWS + r0 + crow] = pr0;
        erow[crow] = pr0;
        g_el[head * NROWS + r0 + crow + 8] = pl1;
        g_er[head * NROWS + r0 + crow + 8] = pr1;
        erow[crow + 8] = pr1;
    }
    __syncthreads();
    if (tid == 0) {
        float m = erow[0];
        #pragma unroll
        for (int i = 1; i < 64; i++) m = fmaxf(m, erow[i]);
        atomicMax(&g_emax_u[layer * 4 + head], f2ord(m));
    }
}

// ---------------- 4. fused attention: split-m with in-kernel last-block fixup ----------------
__global__ __launch_bounds__(128, 3) void attn_kernel(float* __restrict__ dest, int layer,
                                                      int doElu, int toOut) {
    const int head = blockIdx.y;
    const int r0b = blockIdx.x * BRR;
    const int z = blockIdx.z;
    const int msplit = gridDim.z;
    const int mlen = NROWS / msplit;
    const int mstart = z * mlen;
    const int tid = threadIdx.x;
    const int lane = tid & 31, w = tid >> 5;

    __shared__ __align__(16) __half hsB[3][BM * HBP];  // 27.6 KB
    __shared__ __align__(16) float2 bd[2048];          // 16 KB max (mlen <= 2048)
    __shared__ float dens[BRR];
    __shared__ unsigned oldc_s;

    const float emax = ord2f(g_emax_u[layer * 4 + head]);
    for (int i = tid; i < mlen; i += 128) {
        float t = g_er[head * NROWS + mstart + i] - emax;
        bd[i] = make_float2(__expf(t), __expf(ALPHA * t));
    }

    const int rq = lane >> 2;
    const int c2 = (lane & 3) * 2;
    unsigned long long AC[2];
    float dacc[2];
    const unsigned* awp[2];
    #pragma unroll
    for (int i = 0; i < 2; i++) {
        int rowi = w * 16 + rq + i * 8;
        float el = g_el[head * NROWS + r0b + rowi];
        float s0 = el + emax;
        float M = fmaxf(s0, ALPHA * s0);
        AC[i] = packAC(__expf(s0 - M), __expf(ALPHA * s0 - M));
        dacc[i] = 0.f;
        awp[i] = g_adjbits + (size_t)(r0b + rowi) * NW;
    }

    float acc[8][4];
    #pragma unroll
    for (int nt = 0; nt < 8; nt++)
        #pragma unroll
        for (int c = 0; c < 4; c++) acc[nt][c] = 0.f;

    const __half* hb16 = g_h16 + (size_t)head * NROWS * HID;

    const int grp = lane >> 3, li = lane & 7;
    const unsigned hbS = (unsigned)__cvta_generic_to_shared(
        &hsB[0][((grp & 1) * 8 + li) * HBP + (grp >> 1) * 8]);

    int srow[4], sc8[4];
    unsigned sdst[4];
    const unsigned hsBS = (unsigned)__cvta_generic_to_shared(&hsB[0][0]);
    #pragma unroll
    for (int i = 0; i < 4; i++) {
        int idx = tid + i * 128;
        srow[i] = idx >> 3;
        sc8[i] = (idx & 7) * 8;
        sdst[i] = hsBS + (unsigned)((srow[i] * HBP + sc8[i]) * 2);
    }

    const int NCHUNK = mlen / BM;
    #pragma unroll
    for (int i = 0; i < 4; i++)
        cpasync16(sdst[i], &hb16[(size_t)(mstart + srow[i]) * HID + sc8[i]]);
    asm volatile("cp.async.commit_group;" ::: "memory");

    __syncthreads();   // bd ready

    int cur = 0;
    for (int ci = 0; ci < NCHUNK; ci++) {
        const int m0 = mstart + ci * BM;
        const int nxt = (cur == 2) ? 0 : cur + 1;
        if (ci + 1 < NCHUNK) {
            #pragma unroll
            for (int i = 0; i < 4; i++)
                cpasync16(sdst[i] + (unsigned)(nxt * BUFBYTES),
                          &hb16[(size_t)(m0 + BM + srow[i]) * HID + sc8[i]]);
        }
        asm volatile("cp.async.commit_group;" ::: "memory");
        uint2 aj[2];
        #pragma unroll
        for (int i = 0; i < 2; i++) aj[i] = *(const uint2*)(awp[i] + (m0 >> 5));
        asm volatile("cp.async.wait_group 1;" ::: "memory");
        __syncthreads();

        const float4* bd4 = (const float4*)(bd + (m0 - mstart));
        const unsigned hbC = hbS + (unsigned)(cur * BUFBYTES);
        #pragma unroll
        for (int ks = 0; ks < 4; ks++) {
            float4 q0 = bd4[ks * 8 + (lane & 3)];
            float4 q1 = bd4[ks * 8 + 4 + (lane & 3)];
            unsigned afr[4];
            #pragma unroll
            for (int i = 0; i < 2; i++) {
                unsigned wrd = (ks < 2) ? aj[i].x : aj[i].y;
                int sh = (ks & 1) * 16 + c2;
                float2 u0 = mul2(AC[i], *(const unsigned long long*)&q0.x);
                float2 u1 = mul2(AC[i], *(const unsigned long long*)&q0.z);
                float2 u2 = mul2(AC[i], *(const unsigned long long*)&q1.x);
                float2 u3 = mul2(AC[i], *(const unsigned long long*)&q1.z);
                float p0 = ((wrd >> sh) & 1u)       ? fmaxf(u0.x, u0.y) : 0.f;
                float p1 = ((wrd >> (sh + 1)) & 1u) ? fmaxf(u1.x, u1.y) : 0.f;
                float p2 = ((wrd >> (sh + 8)) & 1u) ? fmaxf(u2.x, u2.y) : 0.f;
                float p3 = ((wrd >> (sh + 9)) & 1u) ? fmaxf(u3.x, u3.y) : 0.f;
                dacc[i] += (p0 + p1) + (p2 + p3);
                __half2 hlo = __floats2half2_rn(p0, p1);
                __half2 hhi = __floats2half2_rn(p2, p3);
                afr[i]     = *(unsigned*)&hlo;
                afr[2 + i] = *(unsigned*)&hhi;
            }
            #pragma unroll
            for (int np = 0; np < 4; np++) {
                unsigned b0, b1, b2, b3;
                asm volatile("ldmatrix.sync.aligned.m8n8.x4.trans.shared.b16 {%0,%1,%2,%3}, [%4];"
                             : "=r"(b0), "=r"(b1), "=r"(b2), "=r"(b3)
                             : "r"(hbC + ks * (16 * HBP * 2) + np * 32));
                mma16816(acc[np * 2],     afr[0], afr[1], afr[2], afr[3], b0, b1);
                mma16816(acc[np * 2 + 1], afr[0], afr[1], afr[2], afr[3], b2, b3);
            }
        }
        cur = nxt;
    }

    #pragma unroll
    for (int i = 0; i < 2; i++) {
        dacc[i] += __shfl_xor_sync(0xffffffffu, dacc[i], 1);
        dacc[i] += __shfl_xor_sync(0xffffffffu, dacc[i], 2);
    }

    const int crow = w * 16 + (lane >> 2);
    const int ccol = (lane & 3) * 2;

    // ---- write this block's partial ----
    const int pbase = (blockIdx.x * gridDim.y + head) * msplit;
    const int pidx = pbase + z;
    if ((lane & 3) == 0) {
        #pragma unroll
        for (int i = 0; i < 2; i++)
            g_pden[(size_t)pidx * BRR + w * 16 + rq + i * 8] = dacc[i];
    }
    float* np_ = g_pnum + (size_t)pidx * (BRR * HID);
    #pragma unroll
    for (int nt = 0; nt < 8; nt++) {
        *(float2*)&np_[(size_t)crow * HID + nt * 8 + ccol] =
            make_float2(acc[nt][0], acc[nt][1]);
        *(float2*)&np_[(size_t)(crow + 8) * HID + nt * 8 + ccol] =
            make_float2(acc[nt][2], acc[nt][3]);
    }

    // ---- last-arriving block finalizes (deterministic fixed z-order sum) ----
    __threadfence();
    __syncthreads();
    if (tid == 0)
        oldc_s = atomicAdd(&g_fixcnt[layer * 256 + blockIdx.x * gridDim.y + head], 1u);
    __syncthreads();
    if (oldc_s != (unsigned)(msplit - 1)) return;
    __threadfence();   // acquire: other blocks' partials now visible

    for (int r = tid; r < BRR; r += 128) {
        float d = 0.f;
        for (int zz = 0; zz < msplit; zz++)
            d += g_pden[(size_t)(pbase + zz) * BRR + r];
        dens[r] = 1.0f / d;
    }
    __syncthreads();
    for (int idx = tid; idx < BRR * HID / 2; idx += 128) {
        int row = idx >> 5;
        int c2i = (idx & 31) * 2;
        float n0 = 0.f, n1 = 0.f;
        for (int zz = 0; zz < msplit; zz++) {
            const float* p = g_pnum + (size_t)(pbase + zz) * (BRR * HID) + row * HID + c2i;
            n0 += p[0];
            n1 += p[1];
        }
        float inv = dens[row];
        float v0 = n0 * inv, v1 = n1 * inv;
        if (doElu) {
            v0 = (v0 > 0.f) ? v0 : expm1f(v0);
            v1 = (v1 > 0.f) ? v1 : expm1f(v1);
        }
        if (!toOut) {
            *(__half2*)&g_buf16[(size_t)(r0b + row) * 256 + head * HID + c2i] =
                __floats2half2_rn(v0, v1);
        } else {
            *(float2*)&dest[(size_t)(r0b + row) * HID + c2i] = make_float2(v0, v1);
        }
    }
}

// ---------------- launch ----------------
extern "C" void kernel_launch(void* const* d_in, const int* in_sizes, int n_in,
                              void* d_out, int out_size) {
    const float* x   = (const float*)d_in[0];
    const int*   adj = (const int*)d_in[1];
    const float* W0  = (const float*)d_in[2];
    const float* a0  = (const float*)d_in[3];
    const float* W1  = (const float*)d_in[4];
    const float* a1  = (const float*)d_in[5];
    const float* W2  = (const float*)d_in[6];
    const float* a2  = (const float*)d_in[7];
    float* out = (float*)d_out;

    __half *d_x16, *d_W16, *d_buf16;
    cudaGetSymbolAddress((void**)&d_x16, g_x16);
    cudaGetSymbolAddress((void**)&d_W16, g_W16);
    cudaGetSymbolAddress((void**)&d_buf16, g_buf16);

    pack_adj_kernel<<<NROWS, 128>>>(adj);
    convert_kernel<<<512, 256>>>(x, W0, W1, W2);

    // layer 0: D=128, H=4, msplit=2 (in-kernel fixup)
    gemm16_kernel<<<dim3(64, 4), 128>>>(d_x16, d_W16 + W0OFF, a0, 128, 0);
    attn_kernel<<<dim3(64, 4, 2), 128>>>(nullptr, 0, 1, 0);

    // layer 1: D=256, H=4, msplit=2
    gemm16_kernel<<<dim3(64, 4), 128>>>(d_buf16, d_W16 + W1OFF, a1, 256, 1);
    attn_kernel<<<dim3(64, 4, 2), 128>>>(nullptr, 1, 1, 0);

    // layer 2: D=256, H=1, msplit=8
    gemm16_kernel<<<dim3(64, 1), 128>>>(d_buf16, d_W16 + W2OFF, a2, 256, 2);
    attn_kernel<<<dim3(64, 1, 8), 128>>>(out, 2, 0, 1);
}